// round 3
// baseline (speedup 1.0000x reference)
#include <cuda_runtime.h>
#include <cuda_bf16.h>

#define N_NODES 50000
#define N_EDGES 800000
#define D 128
#define DV 32  // float4 chunks per row

// Scratch for aggregated features h = segment_sum(feature[src], dst).
// __device__ global (no allocation allowed). float4 => 16B alignment for red.v4.
__device__ float4 g_h[(size_t)N_NODES * DV];

// ---------------------------------------------------------------------------
// Kernel 1: zero the accumulator
// ---------------------------------------------------------------------------
__global__ void zero_h_kernel() {
    int i = blockIdx.x * blockDim.x + threadIdx.x;
    if (i < N_NODES * DV) g_h[i] = make_float4(0.f, 0.f, 0.f, 0.f);
}

// ---------------------------------------------------------------------------
// Kernel 2: edge aggregation. One warp per edge, one float4 per lane.
// Gather feature[src] (L2-resident, 25.6MB), scatter-add to g_h[dst] with
// vectorized no-return reduction (red.global.add.v4.f32).
// ---------------------------------------------------------------------------
__global__ void aggregate_kernel(const float4* __restrict__ feat,
                                 const int* __restrict__ src,
                                 const int* __restrict__ dst) {
    long long t = (long long)blockIdx.x * blockDim.x + threadIdx.x;
    int e = (int)(t >> 5);
    if (e >= N_EDGES) return;
    int c = (int)(t & 31);

    // Same address across the warp -> single L1 broadcast transaction each.
    int s = __ldg(src + e);
    int d = __ldg(dst + e);

    float4 v = __ldg(feat + (size_t)s * DV + c);
    float4* p = &g_h[(size_t)d * DV + c];
    asm volatile("red.global.add.v4.f32 [%0], {%1, %2, %3, %4};"
                 :: "l"(p), "f"(v.x), "f"(v.y), "f"(v.z), "f"(v.w)
                 : "memory");
}

// ---------------------------------------------------------------------------
// Kernel 3: y = h @ W^T + b.
// W^T staged in dynamic smem once per block (64KB). One warp per row; lane l
// owns output columns [4l, 4l+4). Grid-stride over rows amortizes the W load.
// smem layout: [ W^T 128x128 | bias 128 | per-warp h staging 8x128 ]
// ---------------------------------------------------------------------------
#define GEMM_BLOCK 256
#define GEMM_WARPS (GEMM_BLOCK / 32)
#define GEMM_SMEM ((D * D + D + GEMM_WARPS * D) * (int)sizeof(float))

__global__ void gemm_kernel(const float* __restrict__ Wm,
                            const float* __restrict__ bias,
                            float* __restrict__ out) {
    extern __shared__ float sm[];
    float* sw = sm;               // W^T: sw[k*D + o]
    float* sb = sm + D * D;       // bias
    float* sh = sb + D;           // per-warp h row staging

    int tid = threadIdx.x;
    // Load W (row-major [o][k]) transposed into smem: coalesced gmem reads.
    for (int i = tid; i < D * D; i += GEMM_BLOCK) {
        int o = i >> 7, k = i & (D - 1);
        sw[k * D + o] = Wm[i];
    }
    if (tid < D) sb[tid] = bias[tid];
    __syncthreads();

    int wid = tid >> 5, lane = tid & 31;
    int warps_total = gridDim.x * GEMM_WARPS;
    int gw = blockIdx.x * GEMM_WARPS + wid;

    const float4* h4 = (const float4*)g_h;
    float4* sh4 = (float4*)(sh + wid * D);
    const float4* sw4 = (const float4*)sw;
    const float4* sb4 = (const float4*)sb;
    float4* out4 = (float4*)out;

    for (int n = gw; n < N_NODES; n += warps_total) {
        // Stage this row's h (128 floats) into smem via the whole warp.
        sh4[lane] = h4[(size_t)n * DV + lane];
        __syncwarp();

        float4 acc = sb4[lane];  // bias for cols 4*lane..4*lane+3
        #pragma unroll 8
        for (int kk = 0; kk < DV; kk++) {
            float4 av = sh4[kk];  // broadcast read (conflict-free)
            const float4* wp = &sw4[(kk * 4) * DV + lane];  // conflict-free
            float4 w0 = wp[0 * DV];
            float4 w1 = wp[1 * DV];
            float4 w2 = wp[2 * DV];
            float4 w3 = wp[3 * DV];
            acc.x += av.x * w0.x; acc.y += av.x * w0.y; acc.z += av.x * w0.z; acc.w += av.x * w0.w;
            acc.x += av.y * w1.x; acc.y += av.y * w1.y; acc.z += av.y * w1.z; acc.w += av.y * w1.w;
            acc.x += av.z * w2.x; acc.y += av.z * w2.y; acc.z += av.z * w2.z; acc.w += av.z * w2.w;
            acc.x += av.w * w3.x; acc.y += av.w * w3.y; acc.z += av.w * w3.z; acc.w += av.w * w3.w;
        }
        out4[(size_t)n * DV + lane] = acc;
        __syncwarp();  // protect staging buffer before next iteration
    }
}

// ---------------------------------------------------------------------------
// Launch: zero -> aggregate -> gemm (serialized on the capture stream).
// Inputs (metadata order): feature f32[50000*128], src i32[800000],
// dst i32[800000], W f32[128*128], b f32[128]. Output f32[50000*128].
// ---------------------------------------------------------------------------
extern "C" void kernel_launch(void* const* d_in, const int* in_sizes, int n_in,
                              void* d_out, int out_size) {
    const float* feature = (const float*)d_in[0];
    const int*   src     = (const int*)d_in[1];
    const int*   dst     = (const int*)d_in[2];
    const float* Wm      = (const float*)d_in[3];
    const float* bias    = (const float*)d_in[4];
    float*       out     = (float*)d_out;

    zero_h_kernel<<<(N_NODES * DV + 255) / 256, 256>>>();

    long long agg_threads = (long long)N_EDGES * 32;
    int agg_blocks = (int)((agg_threads + 255) / 256);
    aggregate_kernel<<<agg_blocks, 256>>>((const float4*)feature, src, dst);

    cudaFuncSetAttribute(gemm_kernel,
                         cudaFuncAttributeMaxDynamicSharedMemorySize, GEMM_SMEM);
    gemm_kernel<<<296, GEMM_BLOCK, GEMM_SMEM>>>(Wm, bias, out);
}

// round 4
// speedup vs baseline: 1.1864x; 1.1864x over previous
#include <cuda_runtime.h>
#include <cuda_bf16.h>

#define N_NODES 50000
#define N_EDGES 800000
#define D 128
#define WPAD 132                      // padded W row (floats): conflict-free LDS.128
#define SW_FLOATS (D * WPAD)          // 16896

// -------- scratch (__device__ globals; no allocation allowed) --------
__device__ int g_deg[N_NODES];
__device__ int g_row[N_NODES + 1];
__device__ int g_cur[N_NODES];
__device__ int g_esrc[N_EDGES];

// ---------------------------------------------------------------------------
// CSR build: zero -> histogram -> scan -> scatter
// ---------------------------------------------------------------------------
__global__ void zero_deg_kernel() {
    int i = blockIdx.x * blockDim.x + threadIdx.x;
    if (i < N_NODES) g_deg[i] = 0;
}

__global__ void hist_kernel(const int* __restrict__ dst) {
    int e = blockIdx.x * blockDim.x + threadIdx.x;
    if (e < N_EDGES) atomicAdd(&g_deg[dst[e]], 1);
}

// Single-block exclusive scan over 50K degrees -> row offsets (+ cursor copy).
__global__ void scan_kernel() {
    __shared__ int ts[1024];
    int t = threadIdx.x;
    const int CHUNK = (N_NODES + 1023) / 1024;   // 49
    int beg = t * CHUNK;
    int end = min(beg + CHUNK, N_NODES);
    int s = 0;
    for (int i = beg; i < end; i++) s += g_deg[i];
    ts[t] = s;
    __syncthreads();
    for (int off = 1; off < 1024; off <<= 1) {   // Hillis-Steele inclusive
        int v = (t >= off) ? ts[t - off] : 0;
        __syncthreads();
        ts[t] += v;
        __syncthreads();
    }
    int run = (t == 0) ? 0 : ts[t - 1];          // exclusive prefix of this chunk
    for (int i = beg; i < end; i++) {
        g_row[i] = run;
        g_cur[i] = run;
        run += g_deg[i];
    }
    if (t == 1023) g_row[N_NODES] = run;         // == N_EDGES
}

__global__ void scatter_kernel(const int* __restrict__ src,
                               const int* __restrict__ dst) {
    int e = blockIdx.x * blockDim.x + threadIdx.x;
    if (e < N_EDGES) {
        int pos = atomicAdd(&g_cur[dst[e]], 1);
        g_esrc[pos] = src[e];
    }
}

// ---------------------------------------------------------------------------
// Fused gather + GEMM.
// One warp processes RPW=4 consecutive nodes per iteration:
//   gather: acc (float4/lane) = sum over CSR edges of feature[src] (L2 hits)
//   stage h rows to per-warp smem, then y = h @ W^T + b with W in smem.
// W stored row-major, 132-float padded rows; lane l owns outputs
// {l, l+32, l+64, l+96}  -> conflict-free smem stores AND float4 loads.
// ---------------------------------------------------------------------------
#define FB 256
#define FW (FB / 32)
#define RPW 4
#define FUSED_SMEM ((SW_FLOATS + D + FW * RPW * D) * (int)sizeof(float))  // 84480 B

__global__ __launch_bounds__(FB, 2)
void fused_kernel(const float4* __restrict__ feat4,
                  const float* __restrict__ Wm,
                  const float* __restrict__ bias,
                  float* __restrict__ out) {
    extern __shared__ float sm[];
    float* sw = sm;                        // W padded: sw[o*WPAD + k]
    float* sb = sm + SW_FLOATS;            // bias
    float* sh = sb + D;                    // staging: [warp][row][k]

    int tid = threadIdx.x;
    for (int i = tid; i < D * D; i += FB) {          // coalesced, conflict-free
        int o = i >> 7, k = i & (D - 1);
        sw[o * WPAD + k] = Wm[i];
    }
    if (tid < D) sb[tid] = bias[tid];
    __syncthreads();

    int wid = tid >> 5, lane = tid & 31;
    int gw = blockIdx.x * FW + wid;
    int nwarps = gridDim.x * FW;
    const int NGROUPS = (N_NODES + RPW - 1) / RPW;

    float* shw = sh + wid * (RPW * D);
    float4* sh4 = (float4*)shw;

    for (int g = gw; g < NGROUPS; g += nwarps) {
        int n0 = g * RPW;

        // ---- gather phase ----
        #pragma unroll
        for (int r = 0; r < RPW; r++) {
            int n = n0 + r;
            float4 acc = make_float4(0.f, 0.f, 0.f, 0.f);
            if (n < N_NODES) {
                int ib = __ldg(&g_row[n]);
                int ie = __ldg(&g_row[n + 1]);
                int i = ib;
                for (; i + 4 <= ie; i += 4) {        // MLP=4 gather pipeline
                    int s0 = __ldg(&g_esrc[i]);
                    int s1 = __ldg(&g_esrc[i + 1]);
                    int s2 = __ldg(&g_esrc[i + 2]);
                    int s3 = __ldg(&g_esrc[i + 3]);
                    float4 v0 = __ldg(&feat4[(size_t)s0 * 32 + lane]);
                    float4 v1 = __ldg(&feat4[(size_t)s1 * 32 + lane]);
                    float4 v2 = __ldg(&feat4[(size_t)s2 * 32 + lane]);
                    float4 v3 = __ldg(&feat4[(size_t)s3 * 32 + lane]);
                    acc.x += (v0.x + v1.x) + (v2.x + v3.x);
                    acc.y += (v0.y + v1.y) + (v2.y + v3.y);
                    acc.z += (v0.z + v1.z) + (v2.z + v3.z);
                    acc.w += (v0.w + v1.w) + (v2.w + v3.w);
                }
                for (; i < ie; i++) {
                    int s = __ldg(&g_esrc[i]);
                    float4 v = __ldg(&feat4[(size_t)s * 32 + lane]);
                    acc.x += v.x; acc.y += v.y; acc.z += v.z; acc.w += v.w;
                }
            }
            sh4[r * 32 + lane] = acc;                // lane-private slot
        }
        __syncwarp();

        // ---- GEMM phase: acc[r][c] = dot(h_r, W[lane+32c]) ----
        float accv[RPW][4];
        #pragma unroll
        for (int r = 0; r < RPW; r++)
            #pragma unroll
            for (int c = 0; c < 4; c++) accv[r][c] = 0.f;

        #pragma unroll 4
        for (int kk = 0; kk < 32; kk++) {
            float4 w[4];
            #pragma unroll
            for (int c = 0; c < 4; c++)              // conflict-free LDS.128
                w[c] = *(const float4*)&sw[(lane + 32 * c) * WPAD + 4 * kk];
            #pragma unroll
            for (int r = 0; r < RPW; r++) {
                float4 a = ((const float4*)(shw + r * D))[kk];  // broadcast
                #pragma unroll
                for (int c = 0; c < 4; c++) {
                    accv[r][c] += a.x * w[c].x;
                    accv[r][c] += a.y * w[c].y;
                    accv[r][c] += a.z * w[c].z;
                    accv[r][c] += a.w * w[c].w;
                }
            }
        }

        // ---- epilogue: bias + coalesced stores ----
        #pragma unroll
        for (int r = 0; r < RPW; r++) {
            int n = n0 + r;
            if (n < N_NODES) {
                #pragma unroll
                for (int c = 0; c < 4; c++)
                    out[(size_t)n * D + lane + 32 * c] = accv[r][c] + sb[lane + 32 * c];
            }
        }
        __syncwarp();   // protect staging before next gather
    }
}

// ---------------------------------------------------------------------------
// Inputs (metadata order): feature f32[50000*128], src i32[800000],
// dst i32[800000], W f32[128*128], b f32[128]. Output f32[50000*128].
// ---------------------------------------------------------------------------
extern "C" void kernel_launch(void* const* d_in, const int* in_sizes, int n_in,
                              void* d_out, int out_size) {
    const float* feature = (const float*)d_in[0];
    const int*   src     = (const int*)d_in[1];
    const int*   dst     = (const int*)d_in[2];
    const float* Wm      = (const float*)d_in[3];
    const float* bias    = (const float*)d_in[4];
    float*       out     = (float*)d_out;

    zero_deg_kernel<<<(N_NODES + 255) / 256, 256>>>();
    hist_kernel<<<(N_EDGES + 255) / 256, 256>>>(dst);
    scan_kernel<<<1, 1024>>>();
    scatter_kernel<<<(N_EDGES + 255) / 256, 256>>>(src, dst);

    cudaFuncSetAttribute(fused_kernel,
                         cudaFuncAttributeMaxDynamicSharedMemorySize, FUSED_SMEM);
    fused_kernel<<<296, FB, FUSED_SMEM>>>((const float4*)feature, Wm, bias, out);
}